// round 16
// baseline (speedup 1.0000x reference)
#include <cuda_runtime.h>
#include <cuda_fp16.h>
#include <cooperative_groups.h>
#include <stdint.h>

namespace cg = cooperative_groups;

#define NN    2048
#define BSZ   16
#define NEGINF (-1e30f)

// ---------------- device scratch (static globals; no runtime allocation) ----
static __device__ float g_at[BSZ];
static __device__ float g_sc[BSZ];
static __device__ float g_csx[BSZ * 8 * 32];
static __device__ float g_csy2[BSZ * 8 * 32];
static __device__ float g_biasB[BSZ * 64];
static __device__ __align__(16) float  g_Wb[BSZ * 96 * 64];
static __device__ __align__(16) __half g_WnH[NN * 96 * 64];   // 25 MB (fp16)
static __device__ __align__(16) float  g_neT[10 * NN];
static __device__ float g_unif[BSZ * NN];
static __device__ float g_w[BSZ * NN * 10];
static __device__ int   g_sidx[BSZ * NN * 10];
static __device__ __align__(16) float g_y1[BSZ * NN * 32];
static __device__ __align__(16) float g_y2[BSZ * NN * 32];

// ---------------- bit-exact threefry-2x32-20, key = (0, 42) -----------------
__device__ __forceinline__ void threefry_0_42(uint32_t x0, uint32_t x1,
                                              uint32_t& o0, uint32_t& o1) {
    const uint32_t ks0 = 0u, ks1 = 42u, ks2 = 0x1BD11BF0u;
    x0 += ks0; x1 += ks1;
#define TF_R(r) { x0 += x1; x1 = (x1 << (r)) | (x1 >> (32 - (r))); x1 ^= x0; }
    TF_R(13) TF_R(15) TF_R(26) TF_R(6)   x0 += ks1; x1 += ks2 + 1u;
    TF_R(17) TF_R(29) TF_R(16) TF_R(24)  x0 += ks2; x1 += ks0 + 2u;
    TF_R(13) TF_R(15) TF_R(26) TF_R(6)   x0 += ks0; x1 += ks1 + 3u;
    TF_R(17) TF_R(29) TF_R(16) TF_R(24)  x0 += ks1; x1 += ks2 + 4u;
    TF_R(13) TF_R(15) TF_R(26) TF_R(6)   x0 += ks2; x1 += ks0 + 5u;
#undef TF_R
    o0 = x0; o1 = x1;
}

__device__ __forceinline__ float jax_noise(uint32_t e) {
    uint32_t o0, o1;
    threefry_0_42(0u, e, o0, o1);
    uint32_t bits = o0 ^ o1;
    float u = __uint_as_float((bits >> 9) | 0x3f800000u) - 1.0f;
    return __fmul_rn(u, 0.01f);
}

__device__ __forceinline__ uint32_t ordkey(float f) {
    uint32_t b = __float_as_uint(f);
    return (b & 0x80000000u) ? ~b : (b | 0x80000000u);
}
__device__ __forceinline__ float ordval(uint32_t u) {
    uint32_t b = (u & 0x80000000u) ? (u ^ 0x80000000u) : ~u;
    return __uint_as_float(b);
}

#define SMEM_BYTES 37632

// ---------------- phase bodies (256 threads each) -----------------------------

__device__ void prep_item(int it, const float* t, const float* nt, const float* p,
                          const float* wp, const float* bp, const float* ne,
                          const float* x, float* smf) {
    int tid = threadIdx.x;
    int b = it % BSZ, role = it / BSZ;
    if (role == 0) {
        float* snt = smf;
        if (tid < 8) snt[tid] = nt[b * 8 + tid];
        __syncthreads();
        if (tid == 0) {
            float at = 0.f;
            for (int d = 0; d < 8; d++) at += snt[d] * t[b * 8 + d];
            g_at[b] = at;
            float pv = p[b];
            g_sc[b] = 1.f + 0.3f * (1.f / (1.f + expf(-pv)));
        }
        if (tid < 64) {
            float acc = 0.f;
#pragma unroll
            for (int d = 0; d < 8; d++) acc += snt[d] * bp[(10 + d) * 64 + tid];
            g_biasB[b * 64 + tid] = acc;
        }
        // zero ALL 256 csy2 partials for this batch (fixed: was 192/256)
        for (int m = tid; m < 256; m += 256) g_csy2[b * 256 + m] = 0.f;
        for (int m = b * 1280 + tid; m < (b + 1) * 1280; m += 256) {
            int n = m / 10, d = m - n * 10;
            g_neT[d * NN + n] = ne[m];
        }
        for (int m = tid; m < 6144; m += 256) {
            float a2 = 0.f;
#pragma unroll
            for (int d = 0; d < 8; d++) a2 += snt[d] * wp[(10 + d) * 6144 + m];
            g_Wb[b * 6144 + m] = a2;
        }
    } else {
        int g = role - 1;
        int c = threadIdx.x & 31, r0 = threadIdx.x >> 5;
        float acc = 0.f;
        int base = b * NN + g * 256;
        for (int n = r0; n < 256; n += 8) acc += x[(base + n) * 32 + c];
        float* sm = smf;
        sm[tid] = acc;
        __syncthreads();
        if (tid < 32) {
            float a = sm[tid];
#pragma unroll
            for (int q = 1; q < 8; q++) a += sm[q * 32 + tid];
            g_csx[(b * 8 + g) * 32 + tid] = a;
        }
    }
}

__device__ void wn_item(int it, const float* ne, const float* wp, float* smf) {
    int tid = threadIdx.x;
    int ng = it / 24, cb = it % 24;
    int col = cb * 256 + tid;
    int n0 = ng * 16;
    float* wps = smf;            // 2560 floats
    float* nes = smf + 2560;     // 160 floats
#pragma unroll
    for (int d = 0; d < 10; d++) wps[d * 256 + tid] = wp[d * 6144 + col];
    if (tid < 160) nes[tid] = ne[n0 * 10 + tid];
    __syncthreads();
    for (int nn = 0; nn < 16; nn++) {
        float acc = 0.f;
#pragma unroll
        for (int d = 0; d < 10; d++) acc += nes[nn * 10 + d] * wps[d * 256 + tid];
        g_WnH[(n0 + nn) * 6144 + col] = __float2half_rn(acc);
    }
}

#define CE(a, b) { if (v[a] < v[b]) { uint64_t _t = v[a]; v[a] = v[b]; v[b] = _t; } }

__device__ void select_item(int it, const float* ne, char* smraw) {
    uint64_t* s_wk = (uint64_t*)smraw;          // 128
    uint64_t* s_ck = (uint64_t*)smraw + 128;    // 16
    int tid = threadIdx.x, lane = tid & 31, w = tid >> 5;
    int jbase = w * 256 + lane * 8;

    for (int ii = 0; ii < 4; ii++) {
        int i = it * 4 + ii;
        float nei[10];
#pragma unroll
        for (int d = 0; d < 10; d++) nei[d] = __ldg(&ne[i * 10 + d]);

        float acc[8] = {0, 0, 0, 0, 0, 0, 0, 0};
#pragma unroll
        for (int d = 0; d < 10; d++) {
            const float4* rp = (const float4*)&g_neT[d * NN + jbase];
            float4 a0 = rp[0], a1 = rp[1];
            float c = nei[d];
            acc[0] += c * a0.x; acc[1] += c * a0.y; acc[2] += c * a0.z; acc[3] += c * a0.w;
            acc[4] += c * a1.x; acc[5] += c * a1.y; acc[6] += c * a1.z; acc[7] += c * a1.w;
        }
        uint64_t v[8];
#pragma unroll
        for (int q = 0; q < 8; q++)
            v[q] = ((uint64_t)ordkey(acc[q]) << 32) | (uint32_t)(2047 - (jbase + q));

        CE(0,1) CE(2,3) CE(4,5) CE(6,7)
        CE(0,2) CE(1,3) CE(4,6) CE(5,7)
        CE(1,2) CE(5,6) CE(0,4) CE(3,7)
        CE(1,5) CE(2,6)
        CE(1,4) CE(3,6)
        CE(2,4) CE(3,5)
        CE(3,4)

        for (int r = 0; r < 16; r++) {
            uint32_t hi = (uint32_t)(v[0] >> 32);
            uint32_t mx = __reduce_max_sync(0xffffffffu, hi);
            uint32_t lo = (hi == mx) ? (uint32_t)v[0] : 0u;
            uint32_t mlo = __reduce_max_sync(0xffffffffu, lo);
            if (lane == 0) s_wk[w * 16 + r] = ((uint64_t)mx << 32) | mlo;
            if (hi == mx && (uint32_t)v[0] == mlo) {
                v[0] = v[1]; v[1] = v[2]; v[2] = v[3]; v[3] = v[4];
                v[4] = v[5]; v[5] = v[6]; v[6] = v[7]; v[7] = 0ull;
            }
        }
        __syncthreads();

        if (w == 0) {
            uint64_t v[4];
#pragma unroll
            for (int q = 0; q < 4; q++) v[q] = s_wk[q * 32 + lane];
            CE(0,1) CE(2,3) CE(0,2) CE(1,3) CE(1,2)
            for (int r = 0; r < 16; r++) {
                uint32_t hi = (uint32_t)(v[0] >> 32);
                uint32_t mx = __reduce_max_sync(0xffffffffu, hi);
                uint32_t lo = (hi == mx) ? (uint32_t)v[0] : 0u;
                uint32_t mlo = __reduce_max_sync(0xffffffffu, lo);
                if (lane == 0) s_ck[r] = ((uint64_t)mx << 32) | mlo;
                if (hi == mx && (uint32_t)v[0] == mlo) {
                    v[0] = v[1]; v[1] = v[2]; v[2] = v[3]; v[3] = 0ull;
                }
            }
        }
        __syncthreads();

        {
            int L = lane & 15;
            int b = w + ((lane & 16) ? 8 : 0);
            uint64_t ck = s_ck[L];
            int   cj = 2047 - (int)(ck & 0x7ffu);
            float cv = ordval((uint32_t)(ck >> 32));

            float s = g_sc[b], at = g_at[b];
            float pre = s * (cv + at);
            float myv = pre > 0.f ? pre : 0.f;
            uint32_t e = (uint32_t)b * 4194304u + (uint32_t)i * 2048u + (uint32_t)cj;
            float key = __fadd_rn(myv, jax_noise(e));

            int half = lane & 16;
            int rank = 0;
#pragma unroll
            for (int kk = 0; kk < 16; kk++) {
                float ok = __shfl_sync(0xffffffffu, key, half + kk);
                rank += (ok > key) || (ok == key && kk < L);
            }
            bool sel = rank < 10;

            float mv = sel ? myv : NEGINF;
#pragma unroll
            for (int off = 8; off; off >>= 1)
                mv = fmaxf(mv, __shfl_xor_sync(0xffffffffu, mv, off));
            float se = sel ? expf(myv - mv) : 0.f;
            float ss = se;
#pragma unroll
            for (int off = 8; off; off >>= 1)
                ss += __shfl_xor_sync(0xffffffffu, ss, off);
            float eu = expf(-mv);
            float Z = ss + 2038.f * eu;
            float unif = eu / Z;

            unsigned mask = __ballot_sync(0xffffffffu, sel);
            unsigned hm = half ? (mask >> 16) : (mask & 0xffffu);
            if (sel) {
                int pos = __popc(hm & ((1u << L) - 1u));
                int base = (b * NN + i) * 10 + pos;
                g_sidx[base] = cj;
                g_w[base] = se / Z - unif;
            }
            if (L == 0) g_unif[b * NN + i] = unif;
        }
        __syncthreads();
    }
}
#undef CE

__device__ void spmv_item(int it, const float* src, const float* cs, const float* x,
                          float* dst, int pass2, float* smf) {
    int lane = threadIdx.x & 31, w = threadIdx.x >> 5;
    int r = it * 8 + w;
    int b = r >> 11;

    const int2*   idp = (const int2*)(g_sidx + r * 10);
    const float2* wwp = (const float2*)(g_w + r * 10);
    int2   idv[5];
    float2 wwv[5];
#pragma unroll
    for (int q = 0; q < 5; q++) { idv[q] = idp[q]; wwv[q] = wwp[q]; }

    float sv[10];
#pragma unroll
    for (int q = 0; q < 5; q++) {
        sv[2 * q]     = src[(b * NN + idv[q].x) * 32 + lane];
        sv[2 * q + 1] = src[(b * NN + idv[q].y) * 32 + lane];
    }
    float cp[8];
#pragma unroll
    for (int g = 0; g < 8; g++) cp[g] = cs[(b * 8 + g) * 32 + lane];
    float un = g_unif[r];
    float xv = pass2 ? x[r * 32 + lane] : 0.f;

    float csv = 0.f;
#pragma unroll
    for (int g = 0; g < 8; g++) csv += cp[g];
    float acc = un * csv;
#pragma unroll
    for (int q = 0; q < 5; q++) {
        acc += wwv[q].x * sv[2 * q];
        acc += wwv[q].y * sv[2 * q + 1];
    }
    if (pass2) acc = 2.f * acc - xv;
    dst[r * 32 + lane] = acc;

    if (!pass2) {
        smf[w * 32 + lane] = acc;
        __syncthreads();
        if (w == 0) {
            float s = smf[lane];
#pragma unroll
            for (int q = 1; q < 8; q++) s += smf[q * 32 + lane];
            int slot = it & 7;
            atomicAdd(&g_csy2[(b * 8 + slot) * 32 + lane], s);
        }
    }
}

__device__ void out1_item(int n, const float* x, const float* y1, const float* y2,
                          const float* ne, const float* bp, float* out, float* smf) {
    int tid = threadIdx.x;
    float* sWt = smf;                 // 6400
    float* sx  = smf + 6400;          // 1536
    float* sbp = smf + 7936;          // 640
    float* snerow = smf + 8576;       // 10
    const uint32_t* wh = (const uint32_t*)(g_WnH + n * 6144);
    for (int m = tid; m < 3072; m += 256) {
        uint32_t pk = wh[m];
        __half2 h2 = *(__half2*)&pk;
        float2 f = __half22float2(h2);
        int e = 2 * m;
        int k = e >> 6, o = e & 63;
        sWt[o * 100 + k]       = f.x;
        sWt[(o + 1) * 100 + k] = f.y;
    }
    for (int m = tid; m < 1536; m += 256) {
        int b = m / 96, k = m - b * 96;
        const float* src = (k < 32) ? x : (k < 64) ? y1 : y2;
        sx[m] = src[(b * NN + n) * 32 + (k & 31)];
    }
    for (int m = tid; m < 640; m += 256) sbp[m] = bp[m];
    if (tid < 10) snerow[tid] = ne[n * 10 + tid];
    __syncthreads();
    int o = tid & 63, g = tid >> 6;   // g in 0..3
    float acc[4] = {0, 0, 0, 0};
    for (int k4 = 0; k4 < 24; k4++) {
        float4 wv = *(const float4*)&sWt[o * 100 + k4 * 4];
#pragma unroll
        for (int q = 0; q < 4; q++) {
            float4 xv = *(const float4*)&sx[(g + 4 * q) * 96 + k4 * 4];
            acc[q] += xv.x * wv.x + xv.y * wv.y + xv.z * wv.z + xv.w * wv.w;
        }
    }
    float bn = 0.f;
#pragma unroll
    for (int d = 0; d < 10; d++) bn += snerow[d] * sbp[d * 64 + o];
#pragma unroll
    for (int q = 0; q < 4; q++) {
        int b = g + 4 * q;
        out[((b * NN) + n) * 64 + o] = acc[q] + bn + g_biasB[b * 64 + o];
    }
}

__device__ void out2_item(int it, const float* x, const float* y1, const float* y2,
                          float* out, float* smf) {
    int nb = it & 31, b = it >> 5;
    int n0 = nb * 64, tid = threadIdx.x;
    float* sWb = smf;           // 3072
    float* sxg = smf + 3072;    // 6208
    {
        const float* srcs[3] = {x, y1, y2};
#pragma unroll
        for (int a = 0; a < 3; a++) {
            const float* s = srcs[a];
            for (int m = tid; m < 2048; m += 256) {
                int rr = m >> 5, c = m & 31;
                sxg[rr * 97 + a * 32 + c] = s[(b * NN + n0 + rr) * 32 + c];
            }
        }
    }
    int o0 = (tid & 15) * 4, tn = tid >> 4;
    float acc[4][4];
#pragma unroll
    for (int rr = 0; rr < 4; rr++)
#pragma unroll
        for (int oo = 0; oo < 4; oo++) acc[rr][oo] = 0.f;

    for (int kc = 0; kc < 2; kc++) {
        __syncthreads();
        for (int m = tid; m < 3072; m += 256)
            sWb[m] = g_Wb[b * 6144 + kc * 3072 + m];
        __syncthreads();
        for (int k = 0; k < 48; k++) {
            float4 wv = *(const float4*)&sWb[k * 64 + o0];
#pragma unroll
            for (int rr = 0; rr < 4; rr++) {
                float xv = sxg[(tn + 16 * rr) * 97 + kc * 48 + k];
                acc[rr][0] += xv * wv.x; acc[rr][1] += xv * wv.y;
                acc[rr][2] += xv * wv.z; acc[rr][3] += xv * wv.w;
            }
        }
    }
#pragma unroll
    for (int rr = 0; rr < 4; rr++) {
        int row = tn + 16 * rr;
        float4* op = (float4*)&out[((b * NN) + (n0 + row)) * 64 + o0];
        float4 cur = *op;
        cur.x += acc[rr][0]; cur.y += acc[rr][1];
        cur.z += acc[rr][2]; cur.w += acc[rr][3];
        *op = cur;
    }
}

// ---------------- the mega kernel --------------------------------------------
__global__ __launch_bounds__(256, 4) void k_mega(const float* __restrict__ t,
                                                 const float* __restrict__ nt,
                                                 const float* __restrict__ p,
                                                 const float* __restrict__ wp,
                                                 const float* __restrict__ bp,
                                                 const float* __restrict__ ne,
                                                 const float* __restrict__ x,
                                                 float* __restrict__ out) {
    cg::grid_group grid = cg::this_grid();
    __shared__ __align__(16) char smraw[SMEM_BYTES];
    float* smf = (float*)smraw;

    float* y1  = g_y1;
    float* y2  = g_y2;

    // phase 0: prep + colsum_x (144 items)
    for (int it = blockIdx.x; it < 144; it += gridDim.x) {
        prep_item(it, t, nt, p, wp, bp, ne, x, smf);
        __syncthreads();
    }
    grid.sync();

    // phase 1: select (512 items)
    for (int it = blockIdx.x; it < 512; it += gridDim.x) {
        select_item(it, ne, smraw);
        __syncthreads();
    }
    grid.sync();

    // phase 2: spmv1 (4096) + Wn GEMM (3072)
    for (int it = blockIdx.x; it < 7168; it += gridDim.x) {
        if (it < 4096) spmv_item(it, x, g_csx, x, y1, 0, smf);
        else           wn_item(it - 4096, ne, wp, smf);
        __syncthreads();
    }
    grid.sync();

    // phase 3: spmv2 (4096)
    for (int it = blockIdx.x; it < 4096; it += gridDim.x) {
        spmv_item(it, y1, g_csy2, x, y2, 1, smf);
        __syncthreads();
    }
    grid.sync();

    // phase 4: out1 (2048)
    for (int it = blockIdx.x; it < 2048; it += gridDim.x) {
        out1_item(it, x, y1, y2, ne, bp, out, smf);
        __syncthreads();
    }
    grid.sync();

    // phase 5: out2 (512)
    for (int it = blockIdx.x; it < 512; it += gridDim.x) {
        out2_item(it, x, y1, y2, out, smf);
        __syncthreads();
    }
}

// ---------------- launch ------------------------------------------------------
extern "C" void kernel_launch(void* const* d_in, const int* in_sizes, int n_in,
                              void* d_out, int out_size) {
    const float* x  = (const float*)d_in[0];
    const float* ne = (const float*)d_in[1];
    const float* t  = (const float*)d_in[2];
    const float* nt = (const float*)d_in[3];
    const float* p  = (const float*)d_in[4];
    const float* wp = (const float*)d_in[5];
    const float* bp = (const float*)d_in[6];
    float* out = (float*)d_out;

    int dev = 0;
    cudaGetDevice(&dev);
    int sms = 0;
    cudaDeviceGetAttribute(&sms, cudaDevAttrMultiProcessorCount, dev);
    int nb = 0;
    cudaOccupancyMaxActiveBlocksPerMultiprocessor(&nb, k_mega, 256, 0);
    if (nb < 1) nb = 1;
    if (sms < 1) sms = 148;
    int grid = sms * nb;

    void* args[] = {(void*)&t, (void*)&nt, (void*)&p, (void*)&wp,
                    (void*)&bp, (void*)&ne, (void*)&x, (void*)&out};
    cudaLaunchCooperativeKernel((void*)k_mega, dim3(grid), dim3(256), args, 0, 0);
}